// round 5
// baseline (speedup 1.0000x reference)
#include <cuda_runtime.h>
#include <cuda_bf16.h>

#define N_NODES 50000
#define N_EDGES 600000
#define F 128

// ---------------- scratch (static device globals; no allocation) ----------------
__device__ float g_h1[N_NODES * F];    // layer-1 output
__device__ float g_h2[N_NODES * F];    // layer-2 output
__device__ float g_agg[N_NODES * F];   // per-layer neighbor sum
__device__ int   g_deg[N_NODES];
__device__ float g_invdeg[N_NODES];

// ---------------- utility kernels ----------------
__global__ void k_zero_deg() {
    int i = blockIdx.x * blockDim.x + threadIdx.x;
    if (i < N_NODES) g_deg[i] = 0;
}

__global__ void k_count_deg(const int* __restrict__ dst) {
    int i = blockIdx.x * blockDim.x + threadIdx.x;
    if (i < N_EDGES) atomicAdd(&g_deg[dst[i]], 1);
}

__global__ void k_invdeg() {
    int i = blockIdx.x * blockDim.x + threadIdx.x;
    if (i < N_NODES) {
        int d = g_deg[i];
        g_invdeg[i] = 1.0f / (float)(d > 0 ? d : 1);
    }
}

__global__ void k_zero_agg() {
    int i = blockIdx.x * blockDim.x + threadIdx.x;   // float4 index
    if (i < N_NODES * F / 4) {
        ((float4*)g_agg)[i] = make_float4(0.f, 0.f, 0.f, 0.f);
    }
}

// ---------------- edge scatter: warp per edge, float4 per lane ----------------
__global__ void __launch_bounds__(256) k_scatter(const float* __restrict__ x,
                                                 const int* __restrict__ src,
                                                 const int* __restrict__ dst) {
    int gid  = blockIdx.x * blockDim.x + threadIdx.x;
    int edge = gid >> 5;
    int lane = gid & 31;
    if (edge >= N_EDGES) return;
    int s = __ldg(&src[edge]);
    int d = __ldg(&dst[edge]);
    float* o = g_agg + (size_t)d * F + lane * 4;
    float4 v = *(const float4*)(x + (size_t)s * F + lane * 4);
    atomicAdd(o + 0, v.x);
    atomicAdd(o + 1, v.y);
    atomicAdd(o + 2, v.z);
    atomicAdd(o + 3, v.w);
}

// ---------------- fused SAGE GEMM: out = act( [x | agg*invdeg] @ [Ws ; Wn] + b ) ----
// BM=64, BN=128 (full width), BK=32, effective K = 256. 256 threads,
// thread tile 4x8 (rows strided by 16, cols strided by 16).
#define BM 64
#define BK 32

__global__ void __launch_bounds__(256) k_gemm(const float* __restrict__ X,
                                              const float* __restrict__ Ws,
                                              const float* __restrict__ Wn,
                                              const float* __restrict__ bias,
                                              float* __restrict__ out,
                                              int relu) {
    __shared__ float As[BM][BK + 4];   // padded row stride 36 (16B-aligned)
    __shared__ float Bs[BK][F];

    int tid = threadIdx.x;
    int tx = tid & 15;          // output-col group
    int ty = tid >> 4;          // output-row group
    int m0 = blockIdx.x * BM;

    float c[4][8];
#pragma unroll
    for (int i = 0; i < 4; i++)
#pragma unroll
        for (int j = 0; j < 8; j++) c[i][j] = 0.f;

    for (int kk = 0; kk < 2 * F; kk += BK) {
        // --- load A tile: 64 rows x 32 k-cols = 512 float4, 2 per thread ---
#pragma unroll
        for (int it = 0; it < 2; it++) {
            int id = tid + 256 * it;
            int m  = id >> 3;
            int k4 = id & 7;
            int row = m0 + m;
            float4 v = make_float4(0.f, 0.f, 0.f, 0.f);
            if (row < N_NODES) {
                int kcol = kk + k4 * 4;
                if (kcol < F) {
                    v = *(const float4*)(X + (size_t)row * F + kcol);
                } else {
                    v = *(const float4*)(g_agg + (size_t)row * F + (kcol - F));
                    float sc = g_invdeg[row];
                    v.x *= sc; v.y *= sc; v.z *= sc; v.w *= sc;
                }
            }
            *(float4*)&As[m][k4 * 4] = v;
        }
        // --- load B tile: 32 k-rows x 128 cols = 1024 float4, 4 per thread ---
#pragma unroll
        for (int it = 0; it < 4; it++) {
            int id = tid + 256 * it;
            int k  = id >> 5;
            int n4 = id & 31;
            int kg = kk + k;
            const float* W = (kg < F) ? (Ws + (size_t)kg * F)
                                      : (Wn + (size_t)(kg - F) * F);
            *(float4*)&Bs[k][n4 * 4] = *(const float4*)(W + n4 * 4);
        }
        __syncthreads();

#pragma unroll
        for (int k = 0; k < BK; k++) {
            float a[4], b[8];
#pragma unroll
            for (int i = 0; i < 4; i++) a[i] = As[ty + 16 * i][k];
#pragma unroll
            for (int j = 0; j < 8; j++) b[j] = Bs[k][tx + 16 * j];
#pragma unroll
            for (int i = 0; i < 4; i++)
#pragma unroll
                for (int j = 0; j < 8; j++) c[i][j] += a[i] * b[j];
        }
        __syncthreads();
    }

#pragma unroll
    for (int i = 0; i < 4; i++) {
        int row = m0 + ty + 16 * i;
        if (row < N_NODES) {
#pragma unroll
            for (int j = 0; j < 8; j++) {
                int col = tx + 16 * j;
                float v = c[i][j] + bias[col];
                if (relu) v = fmaxf(v, 0.f);
                out[(size_t)row * F + col] = v;
            }
        }
    }
}

// ---------------- launch ----------------
extern "C" void kernel_launch(void* const* d_in, const int* in_sizes, int n_in,
                              void* d_out, int out_size) {
    const float* features = (const float*)d_in[0];
    const int*   src      = (const int*)d_in[1];
    const int*   dst      = (const int*)d_in[2];
    const float* W1s = (const float*)d_in[3];
    const float* W1n = (const float*)d_in[4];
    const float* b1  = (const float*)d_in[5];
    const float* W2s = (const float*)d_in[6];
    const float* W2n = (const float*)d_in[7];
    const float* b2  = (const float*)d_in[8];
    const float* W3s = (const float*)d_in[9];
    const float* W3n = (const float*)d_in[10];
    const float* b3  = (const float*)d_in[11];
    float* out = (float*)d_out;

    float *h1, *h2;
    cudaGetSymbolAddress((void**)&h1, g_h1);
    cudaGetSymbolAddress((void**)&h2, g_h2);

    const int ZB = 256;
    int n_blocks    = (N_NODES + ZB - 1) / ZB;
    int e_blocks    = (N_EDGES + ZB - 1) / ZB;
    int agg_blocks  = (N_NODES * F / 4 + ZB - 1) / ZB;
    int scat_blocks = (N_EDGES * 32 + ZB - 1) / ZB;
    int gemm_blocks = (N_NODES + BM - 1) / BM;

    // degrees (once per launch; depends only on dst)
    k_zero_deg<<<n_blocks, ZB>>>();
    k_count_deg<<<e_blocks, ZB>>>(dst);
    k_invdeg<<<n_blocks, ZB>>>();

    // layer 1
    k_zero_agg<<<agg_blocks, ZB>>>();
    k_scatter<<<scat_blocks, ZB>>>(features, src, dst);
    k_gemm<<<gemm_blocks, 256>>>(features, W1s, W1n, b1, h1, 1);

    // layer 2
    k_zero_agg<<<agg_blocks, ZB>>>();
    k_scatter<<<scat_blocks, ZB>>>(h1, src, dst);
    k_gemm<<<gemm_blocks, 256>>>(h1, W2s, W2n, b2, h2, 1);

    // layer 3
    k_zero_agg<<<agg_blocks, ZB>>>();
    k_scatter<<<scat_blocks, ZB>>>(h2, src, dst);
    k_gemm<<<gemm_blocks, 256>>>(h2, W3s, W3n, b3, out, 0);
}

// round 12
// speedup vs baseline: 1.2481x; 1.2481x over previous
#include <cuda_runtime.h>
#include <cuda_bf16.h>
#include <cstdint>

#define N_NODES 50000
#define N_EDGES 600000
#define F 128
#define KDIM 256   // concat [x | mean]

// ---------------- scratch (static device globals; no allocation) ----------------
__device__ float g_h1[N_NODES * F];
__device__ float g_h2[N_NODES * F];
__device__ float g_agg[N_NODES * F];
__device__ int   g_deg[N_NODES];
__device__ float g_invdeg[N_NODES];
__device__ __nv_bfloat16 g_Ahi[(size_t)N_NODES * KDIM];
__device__ __nv_bfloat16 g_Alo[(size_t)N_NODES * KDIM];
__device__ __nv_bfloat16 g_Whi[3 * F * KDIM];   // per layer: [n][k], k contiguous (W^T)
__device__ __nv_bfloat16 g_Wlo[3 * F * KDIM];

// ---------------- small kernels ----------------
__global__ void k_zero_deg() {
    int i = blockIdx.x * blockDim.x + threadIdx.x;
    if (i < N_NODES) g_deg[i] = 0;
}

__global__ void k_count_deg(const int* __restrict__ dst) {
    int i = blockIdx.x * blockDim.x + threadIdx.x;
    if (i < N_EDGES) atomicAdd(&g_deg[dst[i]], 1);
}

__global__ void k_invdeg() {
    int i = blockIdx.x * blockDim.x + threadIdx.x;
    if (i < N_NODES) {
        int d = g_deg[i];
        g_invdeg[i] = 1.0f / (float)(d > 0 ? d : 1);
    }
}

__global__ void k_zero_agg() {
    int i = blockIdx.x * blockDim.x + threadIdx.x;   // float4 index
    if (i < N_NODES * F / 4) {
        ((float4*)g_agg)[i] = make_float4(0.f, 0.f, 0.f, 0.f);
    }
}

// weights -> transposed bf16 hi/lo, all 3 layers in one launch
__global__ void k_convert_W(const float* __restrict__ W1s, const float* __restrict__ W1n,
                            const float* __restrict__ W2s, const float* __restrict__ W2n,
                            const float* __restrict__ W3s, const float* __restrict__ W3n) {
    int i = blockIdx.x * blockDim.x + threadIdx.x;
    if (i >= 3 * F * KDIM) return;
    int layer = i / (F * KDIM);
    int r = i % (F * KDIM);
    int n = r >> 8;          // output col (0..127)
    int k = r & 255;         // concat k  (0..255)
    const float* Ws = (layer == 0) ? W1s : (layer == 1) ? W2s : W3s;
    const float* Wn = (layer == 0) ? W1n : (layer == 1) ? W2n : W3n;
    float w = (k < F) ? Ws[k * F + n] : Wn[(k - F) * F + n];
    __nv_bfloat16 hi = __float2bfloat16(w);
    float lo = w - __bfloat162float(hi);
    g_Whi[i] = hi;
    g_Wlo[i] = __float2bfloat16(lo);
}

// A = [x | agg*invdeg]  -> bf16 hi/lo  [N, 256]
__global__ void k_convert_A(const float* __restrict__ X) {
    int i = blockIdx.x * blockDim.x + threadIdx.x;   // over N*F
    if (i >= N_NODES * F) return;
    int row = i >> 7;
    int col = i & 127;
    float s = X[i];
    float m = g_agg[i] * g_invdeg[row];
    __nv_bfloat16 sh = __float2bfloat16(s);
    __nv_bfloat16 mh = __float2bfloat16(m);
    size_t b = (size_t)row * KDIM + col;
    g_Ahi[b]     = sh;
    g_Alo[b]     = __float2bfloat16(s - __bfloat162float(sh));
    g_Ahi[b + F] = mh;
    g_Alo[b + F] = __float2bfloat16(m - __bfloat162float(mh));
}

// ---------------- edge scatter: warp per edge, float4 per lane (unchanged) -------
__global__ void __launch_bounds__(256) k_scatter(const float* __restrict__ x,
                                                 const int* __restrict__ src,
                                                 const int* __restrict__ dst) {
    int gid  = blockIdx.x * blockDim.x + threadIdx.x;
    int edge = gid >> 5;
    int lane = gid & 31;
    if (edge >= N_EDGES) return;
    int s = __ldg(&src[edge]);
    int d = __ldg(&dst[edge]);
    float* o = g_agg + (size_t)d * F + lane * 4;
    float4 v = *(const float4*)(x + (size_t)s * F + lane * 4);
    atomicAdd(o + 0, v.x);
    atomicAdd(o + 1, v.y);
    atomicAdd(o + 2, v.z);
    atomicAdd(o + 3, v.w);
}

// ---------------- tensor-core GEMM: out = act( A(bf16 split) @ W + b ) ----------
// BM=128, BN=64, BK=32, 256 threads = 8 warps (warp grid 4x2, warp tile 32x32).
// Split-bf16 3-product: D += Ah*Bh + Ah*Bl + Al*Bh  (fp32 accum).
#define BM 128
#define BN 64
#define BK 32
#define STR 40                      // smem row stride (bf16), 80B: conflict-free ldmatrix
#define AS_SZ (BM * STR)            // 5120 bf16
#define BS_SZ (BN * STR)            // 2560 bf16
#define STAGE_SZ (2 * AS_SZ + 2 * BS_SZ)   // 15360 bf16 per stage
#define NSTAGE (KDIM / BK)          // 8
#define GEMM_SMEM_BYTES (2 * STAGE_SZ * 2) // 61440 B

#define LDSM4(R, addr) \
    asm volatile("ldmatrix.sync.aligned.m8n8.x4.shared.b16 {%0,%1,%2,%3}, [%4];" \
        : "=r"((R)[0]), "=r"((R)[1]), "=r"((R)[2]), "=r"((R)[3]) : "r"(addr))

#define MMA_BF16(C, A, B0, B1) \
    asm volatile("mma.sync.aligned.m16n8k16.row.col.f32.bf16.bf16.f32 " \
        "{%0,%1,%2,%3}, {%4,%5,%6,%7}, {%8,%9}, {%0,%1,%2,%3};" \
        : "+f"((C)[0]), "+f"((C)[1]), "+f"((C)[2]), "+f"((C)[3]) \
        : "r"((A)[0]), "r"((A)[1]), "r"((A)[2]), "r"((A)[3]), "r"(B0), "r"(B1))

__global__ void __launch_bounds__(256) k_tc_gemm(const __nv_bfloat16* __restrict__ Whi,
                                                 const __nv_bfloat16* __restrict__ Wlo,
                                                 const float* __restrict__ bias,
                                                 float* __restrict__ out, int relu) {
    extern __shared__ __nv_bfloat16 sm[];
    int tid  = threadIdx.x;
    int lane = tid & 31;
    int warp = tid >> 5;
    int wm = warp >> 1;   // 0..3
    int wn = warp & 1;    // 0..1
    int m0 = blockIdx.x * BM;
    int n0 = blockIdx.y * BN;

    float c[2][4][4];
#pragma unroll
    for (int mt = 0; mt < 2; mt++)
#pragma unroll
        for (int nt = 0; nt < 4; nt++)
#pragma unroll
            for (int q = 0; q < 4; q++) c[mt][nt][q] = 0.f;

    // ---- cp.async stage loader: 1536 x 16B chunks, 6 per thread ----
    auto issue_stage = [&](int s) {
        int k0 = s * BK;
        __nv_bfloat16* base = sm + (s & 1) * STAGE_SZ;
#pragma unroll
        for (int it = 0; it < 6; it++) {
            int cid = tid + it * 256;
            const __nv_bfloat16* src;
            __nv_bfloat16* dstp;
            int sz = 16;
            if (cid < 512) {                       // A_hi: 128 rows x 4 chunks
                int r = cid >> 2, kc = (cid & 3) * 8;
                src = g_Ahi + (size_t)(m0 + r) * KDIM + k0 + kc;
                dstp = base + r * STR + kc;
                if (m0 + r >= N_NODES) sz = 0;
            } else if (cid < 1024) {               // A_lo
                int c2 = cid - 512;
                int r = c2 >> 2, kc = (c2 & 3) * 8;
                src = g_Alo + (size_t)(m0 + r) * KDIM + k0 + kc;
                dstp = base + AS_SZ + r * STR + kc;
                if (m0 + r >= N_NODES) sz = 0;
            } else if (cid < 1280) {               // B_hi: 64 rows x 4 chunks
                int c2 = cid - 1024;
                int r = c2 >> 2, kc = (c2 & 3) * 8;
                src = Whi + (size_t)(n0 + r) * KDIM + k0 + kc;
                dstp = base + 2 * AS_SZ + r * STR + kc;
            } else {                               // B_lo
                int c2 = cid - 1280;
                int r = c2 >> 2, kc = (c2 & 3) * 8;
                src = Wlo + (size_t)(n0 + r) * KDIM + k0 + kc;
                dstp = base + 2 * AS_SZ + BS_SZ + r * STR + kc;
            }
            uint32_t da = (uint32_t)__cvta_generic_to_shared(dstp);
            asm volatile("cp.async.cg.shared.global [%0], [%1], 16, %2;"
                         :: "r"(da), "l"(src), "r"(sz));
        }
        asm volatile("cp.async.commit_group;");
    };

    issue_stage(0);

    for (int s = 0; s < NSTAGE; s++) {
        asm volatile("cp.async.wait_group 0;");
        __syncthreads();
        if (s + 1 < NSTAGE) issue_stage(s + 1);

        __nv_bfloat16* base = sm + (s & 1) * STAGE_SZ;
        __nv_bfloat16* AsH = base;
        __nv_bfloat16* AsL = base + AS_SZ;
        __nv_bfloat16* BsH = base + 2 * AS_SZ;
        __nv_bfloat16* BsL = base + 2 * AS_SZ + BS_SZ;

#pragma unroll
        for (int kq = 0; kq < 2; kq++) {
            int kk = kq * 16;
            uint32_t aH[2][4], aL[2][4], bH[2][4], bL[2][4];

            int ar = lane & 15;
            int ah = lane >> 4;     // 0/1 -> k half
#pragma unroll
            for (int mt = 0; mt < 2; mt++) {
                int mrow = wm * 32 + mt * 16 + ar;
                uint32_t adH = (uint32_t)__cvta_generic_to_shared(AsH + mrow * STR + kk + ah * 8);
                uint32_t adL = (uint32_t)__cvta_generic_to_shared(AsL + mrow * STR + kk + ah * 8);
                LDSM4(aH[mt], adH);
                LDSM4(aL[mt], adL);
            }
            int bq = lane >> 3;     // matrix id 0..3
            int br = lane & 7;
#pragma unroll
            for (int ng = 0; ng < 2; ng++) {
                int bn = wn * 32 + ng * 16 + (bq >> 1) * 8 + br;
                int bk = kk + (bq & 1) * 8;
                uint32_t bdH = (uint32_t)__cvta_generic_to_shared(BsH + bn * STR + bk);
                uint32_t bdL = (uint32_t)__cvta_generic_to_shared(BsL + bn * STR + bk);
                LDSM4(bH[ng], bdH);
                LDSM4(bL[ng], bdL);
            }
#pragma unroll
            for (int mt = 0; mt < 2; mt++)
#pragma unroll
                for (int nt = 0; nt < 4; nt++) {
                    uint32_t* bh = &bH[nt >> 1][(nt & 1) * 2];
                    uint32_t* bl = &bL[nt >> 1][(nt & 1) * 2];
                    MMA_BF16(c[mt][nt], aH[mt], bh[0], bh[1]);
                    MMA_BF16(c[mt][nt], aH[mt], bl[0], bl[1]);
                    MMA_BF16(c[mt][nt], aL[mt], bh[0], bh[1]);
                }
        }
    }

    // ---- epilogue: bias + optional relu, float2 stores ----
#pragma unroll
    for (int mt = 0; mt < 2; mt++) {
        int r0 = m0 + wm * 32 + mt * 16 + (lane >> 2);
#pragma unroll
        for (int nt = 0; nt < 4; nt++) {
            int col = n0 + wn * 32 + nt * 8 + (lane & 3) * 2;
            float b0 = __ldg(&bias[col]);
            float b1 = __ldg(&bias[col + 1]);
            float v0 = c[mt][nt][0] + b0;
            float v1 = c[mt][nt][1] + b1;
            float v2 = c[mt][nt][2] + b0;
            float v3 = c[mt][nt][3] + b1;
            if (relu) {
                v0 = fmaxf(v0, 0.f); v1 = fmaxf(v1, 0.f);
                v2 = fmaxf(v2, 0.f); v3 = fmaxf(v3, 0.f);
            }
            if (r0 < N_NODES)
                *(float2*)(out + (size_t)r0 * F + col) = make_float2(v0, v1);
            if (r0 + 8 < N_NODES)
                *(float2*)(out + (size_t)(r0 + 8) * F + col) = make_float2(v2, v3);
        }
    }
}

// ---------------- launch ----------------
extern "C" void kernel_launch(void* const* d_in, const int* in_sizes, int n_in,
                              void* d_out, int out_size) {
    const float* features = (const float*)d_in[0];
    const int*   src      = (const int*)d_in[1];
    const int*   dst      = (const int*)d_in[2];
    const float* W1s = (const float*)d_in[3];
    const float* W1n = (const float*)d_in[4];
    const float* b1  = (const float*)d_in[5];
    const float* W2s = (const float*)d_in[6];
    const float* W2n = (const float*)d_in[7];
    const float* b2  = (const float*)d_in[8];
    const float* W3s = (const float*)d_in[9];
    const float* W3n = (const float*)d_in[10];
    const float* b3  = (const float*)d_in[11];
    float* out = (float*)d_out;

    float *h1, *h2;
    __nv_bfloat16 *whi, *wlo;
    cudaGetSymbolAddress((void**)&h1, g_h1);
    cudaGetSymbolAddress((void**)&h2, g_h2);
    cudaGetSymbolAddress((void**)&whi, g_Whi);
    cudaGetSymbolAddress((void**)&wlo, g_Wlo);

    // Idempotent, not a stream op (capture-safe); no static guard per harness rules.
    cudaFuncSetAttribute(k_tc_gemm, cudaFuncAttributeMaxDynamicSharedMemorySize,
                         GEMM_SMEM_BYTES);

    const int ZB = 256;
    int n_blocks    = (N_NODES + ZB - 1) / ZB;
    int e_blocks    = (N_EDGES + ZB - 1) / ZB;
    int agg_blocks  = (N_NODES * F / 4 + ZB - 1) / ZB;
    int scat_blocks = (N_EDGES * 32 + ZB - 1) / ZB;
    int cw_blocks   = (3 * F * KDIM + ZB - 1) / ZB;
    int ca_blocks   = (N_NODES * F + ZB - 1) / ZB;
    dim3 gemm_grid((N_NODES + BM - 1) / BM, F / BN);

    // weights -> bf16 hi/lo transposed (per replay; deterministic)
    k_convert_W<<<cw_blocks, ZB>>>(W1s, W1n, W2s, W2n, W3s, W3n);

    // degrees
    k_zero_deg<<<n_blocks, ZB>>>();
    k_count_deg<<<e_blocks, ZB>>>(dst);
    k_invdeg<<<n_blocks, ZB>>>();

    // layer 1
    k_zero_agg<<<agg_blocks, ZB>>>();
    k_scatter<<<scat_blocks, ZB>>>(features, src, dst);
    k_convert_A<<<ca_blocks, ZB>>>(features);
    k_tc_gemm<<<gemm_grid, 256, GEMM_SMEM_BYTES>>>(whi + 0 * F * KDIM, wlo + 0 * F * KDIM, b1, h1, 1);

    // layer 2
    k_zero_agg<<<agg_blocks, ZB>>>();
    k_scatter<<<scat_blocks, ZB>>>(h1, src, dst);
    k_convert_A<<<ca_blocks, ZB>>>(h1);
    k_tc_gemm<<<gemm_grid, 256, GEMM_SMEM_BYTES>>>(whi + 1 * F * KDIM, wlo + 1 * F * KDIM, b2, h2, 1);

    // layer 3
    k_zero_agg<<<agg_blocks, ZB>>>();
    k_scatter<<<scat_blocks, ZB>>>(h2, src, dst);
    k_convert_A<<<ca_blocks, ZB>>>(h2);
    k_tc_gemm<<<gemm_grid, 256, GEMM_SMEM_BYTES>>>(whi + 2 * F * KDIM, wlo + 2 * F * KDIM, b3, out, 0);
}

// round 13
// speedup vs baseline: 2.7420x; 2.1969x over previous
#include <cuda_runtime.h>
#include <cuda_bf16.h>
#include <cstdint>

#define N_NODES 50000
#define N_EDGES 600000
#define F 128
#define KDIM 256   // concat [x | mean]

// ---------------- scratch (static device globals; no allocation) ----------------
__device__ float g_h1[N_NODES * F];
__device__ float g_h2[N_NODES * F];
__device__ int   g_deg[N_NODES];
__device__ int   g_rowstart[N_NODES + 1];
__device__ int   g_cursor[N_NODES];
__device__ int   g_csr[N_EDGES];
__device__ __nv_bfloat16 g_Ahi[(size_t)N_NODES * KDIM];
__device__ __nv_bfloat16 g_Alo[(size_t)N_NODES * KDIM];
__device__ __nv_bfloat16 g_Whi[3 * F * KDIM];   // per layer: [n][k], k contiguous (W^T)
__device__ __nv_bfloat16 g_Wlo[3 * F * KDIM];

// ---------------- CSR build ----------------
__global__ void k_zero_deg() {
    int i = blockIdx.x * blockDim.x + threadIdx.x;
    if (i < N_NODES) g_deg[i] = 0;
}

__global__ void k_count_deg(const int* __restrict__ dst) {
    int i = blockIdx.x * blockDim.x + threadIdx.x;
    if (i < N_EDGES) atomicAdd(&g_deg[dst[i]], 1);
}

// single-block exclusive scan of degrees -> rowstart, cursor
#define SCAN_T 1024
#define SCAN_CHUNK ((N_NODES + SCAN_T - 1) / SCAN_T)   // 49
__global__ void __launch_bounds__(SCAN_T) k_scan() {
    __shared__ int ssum[SCAN_T];
    int t = threadIdx.x;
    int lo = t * SCAN_CHUNK;
    int hi = min(lo + SCAN_CHUNK, N_NODES);
    int s = 0;
    for (int i = lo; i < hi; i++) s += g_deg[i];
    ssum[t] = s;
    __syncthreads();
    for (int off = 1; off < SCAN_T; off <<= 1) {
        int v = (t >= off) ? ssum[t - off] : 0;
        __syncthreads();
        ssum[t] += v;
        __syncthreads();
    }
    int run = (t == 0) ? 0 : ssum[t - 1];
    for (int i = lo; i < hi; i++) {
        g_rowstart[i] = run;
        g_cursor[i]   = run;
        run += g_deg[i];
    }
    if (t == SCAN_T - 1) g_rowstart[N_NODES] = N_EDGES;
}

__global__ void k_fill(const int* __restrict__ src, const int* __restrict__ dst) {
    int i = blockIdx.x * blockDim.x + threadIdx.x;
    if (i < N_EDGES) {
        int slot = atomicAdd(&g_cursor[dst[i]], 1);
        g_csr[slot] = src[i];
    }
}

// weights -> transposed bf16 hi/lo, all 3 layers in one launch
__global__ void k_convert_W(const float* __restrict__ W1s, const float* __restrict__ W1n,
                            const float* __restrict__ W2s, const float* __restrict__ W2n,
                            const float* __restrict__ W3s, const float* __restrict__ W3n) {
    int i = blockIdx.x * blockDim.x + threadIdx.x;
    if (i >= 3 * F * KDIM) return;
    int layer = i / (F * KDIM);
    int r = i % (F * KDIM);
    int n = r >> 8;          // output col (0..127)
    int k = r & 255;         // concat k  (0..255)
    const float* Ws = (layer == 0) ? W1s : (layer == 1) ? W2s : W3s;
    const float* Wn = (layer == 0) ? W1n : (layer == 1) ? W2n : W3n;
    float w = (k < F) ? Ws[k * F + n] : Wn[(k - F) * F + n];
    __nv_bfloat16 hi = __float2bfloat16(w);
    float lo = w - __bfloat162float(hi);
    g_Whi[i] = hi;
    g_Wlo[i] = __float2bfloat16(lo);
}

// ---------------- fused gather-mean + bf16 split conversion ----------------
// warp per node; lane owns 4 contiguous features. Writes A = [x | mean] hi/lo.
struct BF4 { __nv_bfloat16 v[4]; };

__device__ __forceinline__ void split_store(float4 f, __nv_bfloat16* hi, __nv_bfloat16* lo) {
    BF4 h, l;
    float a[4] = {f.x, f.y, f.z, f.w};
#pragma unroll
    for (int j = 0; j < 4; j++) {
        h.v[j] = __float2bfloat16(a[j]);
        l.v[j] = __float2bfloat16(a[j] - __bfloat162float(h.v[j]));
    }
    *(BF4*)hi = h;
    *(BF4*)lo = l;
}

__global__ void __launch_bounds__(256) k_gather_convert(const float* __restrict__ X) {
    int gid  = blockIdx.x * blockDim.x + threadIdx.x;
    int node = gid >> 5;
    int lane = gid & 31;
    if (node >= N_NODES) return;
    int rs = g_rowstart[node];
    int re = g_rowstart[node + 1];

    float4 acc = make_float4(0.f, 0.f, 0.f, 0.f);
    for (int e = rs; e < re; e++) {
        int s = __ldg(&g_csr[e]);
        float4 v = *(const float4*)(X + (size_t)s * F + lane * 4);
        acc.x += v.x; acc.y += v.y; acc.z += v.z; acc.w += v.w;
    }
    float inv = 1.0f / (float)max(re - rs, 1);
    acc.x *= inv; acc.y *= inv; acc.z *= inv; acc.w *= inv;

    float4 self = *(const float4*)(X + (size_t)node * F + lane * 4);

    size_t b = (size_t)node * KDIM + lane * 4;
    split_store(self, g_Ahi + b,     g_Alo + b);
    split_store(acc,  g_Ahi + b + F, g_Alo + b + F);
}

// ---------------- tensor-core GEMM: out = act( A(bf16 split) @ W + b ) ----------
// BM=128, BN=64, BK=32, 256 threads = 8 warps (warp grid 4x2, warp tile 32x32).
// Split-bf16 3-product: D += Ah*Bh + Ah*Bl + Al*Bh  (fp32 accum).
#define BM 128
#define BN 64
#define BK 32
#define STR 40                      // smem row stride (bf16), 80B: conflict-free ldmatrix
#define AS_SZ (BM * STR)            // 5120 bf16
#define BS_SZ (BN * STR)            // 2560 bf16
#define STAGE_SZ (2 * AS_SZ + 2 * BS_SZ)   // 15360 bf16 per stage
#define NSTAGE (KDIM / BK)          // 8
#define GEMM_SMEM_BYTES (2 * STAGE_SZ * 2) // 61440 B

#define LDSM4(R, addr) \
    asm volatile("ldmatrix.sync.aligned.m8n8.x4.shared.b16 {%0,%1,%2,%3}, [%4];" \
        : "=r"((R)[0]), "=r"((R)[1]), "=r"((R)[2]), "=r"((R)[3]) : "r"(addr))

#define MMA_BF16(C, A, B0, B1) \
    asm volatile("mma.sync.aligned.m16n8k16.row.col.f32.bf16.bf16.f32 " \
        "{%0,%1,%2,%3}, {%4,%5,%6,%7}, {%8,%9}, {%0,%1,%2,%3};" \
        : "+f"((C)[0]), "+f"((C)[1]), "+f"((C)[2]), "+f"((C)[3]) \
        : "r"((A)[0]), "r"((A)[1]), "r"((A)[2]), "r"((A)[3]), "r"(B0), "r"(B1))

__global__ void __launch_bounds__(256) k_tc_gemm(const __nv_bfloat16* __restrict__ Whi,
                                                 const __nv_bfloat16* __restrict__ Wlo,
                                                 const float* __restrict__ bias,
                                                 float* __restrict__ out, int relu) {
    extern __shared__ __nv_bfloat16 sm[];
    int tid  = threadIdx.x;
    int lane = tid & 31;
    int warp = tid >> 5;
    int wm = warp >> 1;   // 0..3
    int wn = warp & 1;    // 0..1
    int m0 = blockIdx.x * BM;
    int n0 = blockIdx.y * BN;

    float c[2][4][4];
#pragma unroll
    for (int mt = 0; mt < 2; mt++)
#pragma unroll
        for (int nt = 0; nt < 4; nt++)
#pragma unroll
            for (int q = 0; q < 4; q++) c[mt][nt][q] = 0.f;

    // ---- cp.async stage loader: 1536 x 16B chunks, 6 per thread ----
    auto issue_stage = [&](int s) {
        int k0 = s * BK;
        __nv_bfloat16* base = sm + (s & 1) * STAGE_SZ;
#pragma unroll
        for (int it = 0; it < 6; it++) {
            int cid = tid + it * 256;
            const __nv_bfloat16* src;
            __nv_bfloat16* dstp;
            int sz = 16;
            if (cid < 512) {                       // A_hi: 128 rows x 4 chunks
                int r = cid >> 2, kc = (cid & 3) * 8;
                src = g_Ahi + (size_t)(m0 + r) * KDIM + k0 + kc;
                dstp = base + r * STR + kc;
                if (m0 + r >= N_NODES) sz = 0;
            } else if (cid < 1024) {               // A_lo
                int c2 = cid - 512;
                int r = c2 >> 2, kc = (c2 & 3) * 8;
                src = g_Alo + (size_t)(m0 + r) * KDIM + k0 + kc;
                dstp = base + AS_SZ + r * STR + kc;
                if (m0 + r >= N_NODES) sz = 0;
            } else if (cid < 1280) {               // B_hi: 64 rows x 4 chunks
                int c2 = cid - 1024;
                int r = c2 >> 2, kc = (c2 & 3) * 8;
                src = Whi + (size_t)(n0 + r) * KDIM + k0 + kc;
                dstp = base + 2 * AS_SZ + r * STR + kc;
            } else {                               // B_lo
                int c2 = cid - 1280;
                int r = c2 >> 2, kc = (c2 & 3) * 8;
                src = Wlo + (size_t)(n0 + r) * KDIM + k0 + kc;
                dstp = base + 2 * AS_SZ + BS_SZ + r * STR + kc;
            }
            uint32_t da = (uint32_t)__cvta_generic_to_shared(dstp);
            asm volatile("cp.async.cg.shared.global [%0], [%1], 16, %2;"
                         :: "r"(da), "l"(src), "r"(sz));
        }
        asm volatile("cp.async.commit_group;");
    };

    issue_stage(0);

    for (int s = 0; s < NSTAGE; s++) {
        asm volatile("cp.async.wait_group 0;");
        __syncthreads();
        if (s + 1 < NSTAGE) issue_stage(s + 1);

        __nv_bfloat16* base = sm + (s & 1) * STAGE_SZ;
        __nv_bfloat16* AsH = base;
        __nv_bfloat16* AsL = base + AS_SZ;
        __nv_bfloat16* BsH = base + 2 * AS_SZ;
        __nv_bfloat16* BsL = base + 2 * AS_SZ + BS_SZ;

#pragma unroll
        for (int kq = 0; kq < 2; kq++) {
            int kk = kq * 16;
            uint32_t aH[2][4], aL[2][4], bH[2][4], bL[2][4];

            int ar = lane & 15;
            int ah = lane >> 4;     // 0/1 -> k half
#pragma unroll
            for (int mt = 0; mt < 2; mt++) {
                int mrow = wm * 32 + mt * 16 + ar;
                uint32_t adH = (uint32_t)__cvta_generic_to_shared(AsH + mrow * STR + kk + ah * 8);
                uint32_t adL = (uint32_t)__cvta_generic_to_shared(AsL + mrow * STR + kk + ah * 8);
                LDSM4(aH[mt], adH);
                LDSM4(aL[mt], adL);
            }
            int bq = lane >> 3;     // matrix id 0..3
            int br = lane & 7;
#pragma unroll
            for (int ng = 0; ng < 2; ng++) {
                int bn = wn * 32 + ng * 16 + (bq >> 1) * 8 + br;
                int bk = kk + (bq & 1) * 8;
                uint32_t bdH = (uint32_t)__cvta_generic_to_shared(BsH + bn * STR + bk);
                uint32_t bdL = (uint32_t)__cvta_generic_to_shared(BsL + bn * STR + bk);
                LDSM4(bH[ng], bdH);
                LDSM4(bL[ng], bdL);
            }
#pragma unroll
            for (int mt = 0; mt < 2; mt++)
#pragma unroll
                for (int nt = 0; nt < 4; nt++) {
                    uint32_t* bh = &bH[nt >> 1][(nt & 1) * 2];
                    uint32_t* bl = &bL[nt >> 1][(nt & 1) * 2];
                    MMA_BF16(c[mt][nt], aH[mt], bh[0], bh[1]);
                    MMA_BF16(c[mt][nt], aH[mt], bl[0], bl[1]);
                    MMA_BF16(c[mt][nt], aL[mt], bh[0], bh[1]);
                }
        }
    }

    // ---- epilogue: bias + optional relu, float2 stores ----
#pragma unroll
    for (int mt = 0; mt < 2; mt++) {
        int r0 = m0 + wm * 32 + mt * 16 + (lane >> 2);
#pragma unroll
        for (int nt = 0; nt < 4; nt++) {
            int col = n0 + wn * 32 + nt * 8 + (lane & 3) * 2;
            float b0 = __ldg(&bias[col]);
            float b1 = __ldg(&bias[col + 1]);
            float v0 = c[mt][nt][0] + b0;
            float v1 = c[mt][nt][1] + b1;
            float v2 = c[mt][nt][2] + b0;
            float v3 = c[mt][nt][3] + b1;
            if (relu) {
                v0 = fmaxf(v0, 0.f); v1 = fmaxf(v1, 0.f);
                v2 = fmaxf(v2, 0.f); v3 = fmaxf(v3, 0.f);
            }
            if (r0 < N_NODES)
                *(float2*)(out + (size_t)r0 * F + col) = make_float2(v0, v1);
            if (r0 + 8 < N_NODES)
                *(float2*)(out + (size_t)(r0 + 8) * F + col) = make_float2(v2, v3);
        }
    }
}

// ---------------- launch ----------------
extern "C" void kernel_launch(void* const* d_in, const int* in_sizes, int n_in,
                              void* d_out, int out_size) {
    const float* features = (const float*)d_in[0];
    const int*   src      = (const int*)d_in[1];
    const int*   dst      = (const int*)d_in[2];
    const float* W1s = (const float*)d_in[3];
    const float* W1n = (const float*)d_in[4];
    const float* b1  = (const float*)d_in[5];
    const float* W2s = (const float*)d_in[6];
    const float* W2n = (const float*)d_in[7];
    const float* b2  = (const float*)d_in[8];
    const float* W3s = (const float*)d_in[9];
    const float* W3n = (const float*)d_in[10];
    const float* b3  = (const float*)d_in[11];
    float* out = (float*)d_out;

    float *h1, *h2;
    __nv_bfloat16 *whi, *wlo;
    cudaGetSymbolAddress((void**)&h1, g_h1);
    cudaGetSymbolAddress((void**)&h2, g_h2);
    cudaGetSymbolAddress((void**)&whi, g_Whi);
    cudaGetSymbolAddress((void**)&wlo, g_Wlo);

    // Idempotent, not a stream op (capture-safe); no static guard per harness rules.
    cudaFuncSetAttribute(k_tc_gemm, cudaFuncAttributeMaxDynamicSharedMemorySize,
                         GEMM_SMEM_BYTES);

    const int ZB = 256;
    int n_blocks   = (N_NODES + ZB - 1) / ZB;
    int e_blocks   = (N_EDGES + ZB - 1) / ZB;
    int cw_blocks  = (3 * F * KDIM + ZB - 1) / ZB;
    int gc_blocks  = (N_NODES * 32 + ZB - 1) / ZB;   // warp per node
    dim3 gemm_grid((N_NODES + BM - 1) / BM, F / BN);

    // weights -> bf16 hi/lo transposed
    k_convert_W<<<cw_blocks, ZB>>>(W1s, W1n, W2s, W2n, W3s, W3n);

    // CSR build (depends only on src/dst; once per launch)
    k_zero_deg<<<n_blocks, ZB>>>();
    k_count_deg<<<e_blocks, ZB>>>(dst);
    k_scan<<<1, SCAN_T>>>();
    k_fill<<<e_blocks, ZB>>>(src, dst);

    // layer 1
    k_gather_convert<<<gc_blocks, ZB>>>(features);
    k_tc_gemm<<<gemm_grid, 256, GEMM_SMEM_BYTES>>>(whi + 0 * F * KDIM, wlo + 0 * F * KDIM, b1, h1, 1);

    // layer 2
    k_gather_convert<<<gc_blocks, ZB>>>(h1);
    k_tc_gemm<<<gemm_grid, 256, GEMM_SMEM_BYTES>>>(whi + 1 * F * KDIM, wlo + 1 * F * KDIM, b2, h2, 1);

    // layer 3
    k_gather_convert<<<gc_blocks, ZB>>>(h2);
    k_tc_gemm<<<gemm_grid, 256, GEMM_SMEM_BYTES>>>(whi + 2 * F * KDIM, wlo + 2 * F * KDIM, b3, out, 0);
}